// round 10
// baseline (speedup 1.0000x reference)
#include <cuda_runtime.h>
#include <cuda_bf16.h>
#include <stdint.h>
#include <math.h>

#define N_RNA  4096
#define N_ATAC 8192
#define IN_C   256
#define HID    128
#define NHEAD  2
#define DH     64
#define TOPK   10
#define THR    0.8f

// ---------------- device scratch ------------------------------------------
__device__ float g_q   [N_RNA  * HID];
__device__ float g_k   [N_ATAC * HID];
__device__ float g_vr  [N_RNA  * HID];
__device__ float g_va  [N_ATAC * HID];
__device__ float g_S   [(size_t)NHEAD * N_RNA * N_ATAC];   // 256 MB masked scores
__device__ float g_ragg[N_RNA  * HID];
__device__ float g_aagg[N_ATAC * HID];
__device__ float g_catr[N_RNA  * 2 * HID];
__device__ float g_cata[N_ATAC * 2 * HID];
__device__ __nv_bfloat16 g_qhi[N_RNA  * HID];
__device__ __nv_bfloat16 g_qlo[N_RNA  * HID];
__device__ __nv_bfloat16 g_khi[N_ATAC * HID];
__device__ __nv_bfloat16 g_klo[N_ATAC * HID];

// ---------------- mma.sync helper (sm_80+, works at target sm_103) ---------
__device__ __forceinline__ void mma_bf16(float* c, const uint32_t* a, const uint32_t* b) {
    asm volatile("mma.sync.aligned.m16n8k16.row.col.f32.bf16.bf16.f32 "
        "{%0,%1,%2,%3}, {%4,%5,%6,%7}, {%8,%9}, {%0,%1,%2,%3};"
        : "+f"(c[0]), "+f"(c[1]), "+f"(c[2]), "+f"(c[3])
        : "r"(a[0]), "r"(a[1]), "r"(a[2]), "r"(a[3]), "r"(b[0]), "r"(b[1]));
}

// ---------------- zero atac aggregation buffer -----------------------------
__global__ void zero_aagg_kernel() {
    int i = blockIdx.x * blockDim.x + threadIdx.x;
    reinterpret_cast<float4*>(g_aagg)[i] = make_float4(0.f, 0.f, 0.f, 0.f);
}

// ---------------- fp32 -> (hi, lo) bf16 split ------------------------------
__global__ __launch_bounds__(256)
void convert_kernel(const float* __restrict__ src,
                    __nv_bfloat16* __restrict__ hi, __nv_bfloat16* __restrict__ lo)
{
    int i = blockIdx.x * 256 + threadIdx.x;          // float4 index
    float4 x = reinterpret_cast<const float4*>(src)[i];
    __nv_bfloat16 h0 = __float2bfloat16_rn(x.x);
    __nv_bfloat16 h1 = __float2bfloat16_rn(x.y);
    __nv_bfloat16 h2 = __float2bfloat16_rn(x.z);
    __nv_bfloat16 h3 = __float2bfloat16_rn(x.w);
    __nv_bfloat16 l0 = __float2bfloat16_rn(x.x - __bfloat162float(h0));
    __nv_bfloat16 l1 = __float2bfloat16_rn(x.y - __bfloat162float(h1));
    __nv_bfloat16 l2 = __float2bfloat16_rn(x.z - __bfloat162float(h2));
    __nv_bfloat16 l3 = __float2bfloat16_rn(x.w - __bfloat162float(h3));
    uint2 hp, lp;
    hp.x = (uint32_t)__bfloat16_as_ushort(h0) | ((uint32_t)__bfloat16_as_ushort(h1) << 16);
    hp.y = (uint32_t)__bfloat16_as_ushort(h2) | ((uint32_t)__bfloat16_as_ushort(h3) << 16);
    lp.x = (uint32_t)__bfloat16_as_ushort(l0) | ((uint32_t)__bfloat16_as_ushort(l1) << 16);
    lp.y = (uint32_t)__bfloat16_as_ushort(l2) | ((uint32_t)__bfloat16_as_ushort(l3) << 16);
    reinterpret_cast<uint2*>(hi)[i] = hp;
    reinterpret_cast<uint2*>(lo)[i] = lp;
}

// ---------------- GEMM (single output): C[N x 128] = X @ W + b -------------
#define GBK 16
__global__ __launch_bounds__(256)
void gemm_bias_kernel(const float* __restrict__ X, int K,
                      const float* __restrict__ W,
                      const float* __restrict__ b,
                      float* __restrict__ C, int ldc)
{
    __shared__ float Xs[GBK * 36];
    __shared__ float Ws[GBK * 128];
    const int t   = threadIdx.x;
    const int r0  = blockIdx.x * 32;
    const int rg4 = (t >> 5) * 4;
    const int cg  = (t & 31) * 4;

    float acc[4][4];
#pragma unroll
    for (int i = 0; i < 4; i++)
#pragma unroll
        for (int j = 0; j < 4; j++) acc[i][j] = 0.f;

    for (int k0 = 0; k0 < K; k0 += GBK) {
#pragma unroll
        for (int i = 0; i < 2; i++) {
            int idx = t + i * 256;
            int row = idx >> 4;
            int kk  = idx & 15;
            Xs[kk * 36 + row] = X[(size_t)(r0 + row) * K + k0 + kk];
        }
#pragma unroll
        for (int i = 0; i < 2; i++) {
            int row = (t >> 5) + i * 8;
            int col = (t & 31) * 4;
            float4 w4 = *reinterpret_cast<const float4*>(&W[(size_t)(k0 + row) * 128 + col]);
            *reinterpret_cast<float4*>(&Ws[row * 128 + col]) = w4;
        }
        __syncthreads();
#pragma unroll
        for (int kk = 0; kk < GBK; kk++) {
            float4 wv = *reinterpret_cast<const float4*>(&Ws[kk * 128 + cg]);
            float4 xv = *reinterpret_cast<const float4*>(&Xs[kk * 36 + rg4]);
            acc[0][0] += xv.x * wv.x; acc[0][1] += xv.x * wv.y; acc[0][2] += xv.x * wv.z; acc[0][3] += xv.x * wv.w;
            acc[1][0] += xv.y * wv.x; acc[1][1] += xv.y * wv.y; acc[1][2] += xv.y * wv.z; acc[1][3] += xv.y * wv.w;
            acc[2][0] += xv.z * wv.x; acc[2][1] += xv.z * wv.y; acc[2][2] += xv.z * wv.z; acc[2][3] += xv.z * wv.w;
            acc[3][0] += xv.w * wv.x; acc[3][1] += xv.w * wv.y; acc[3][2] += xv.w * wv.z; acc[3][3] += xv.w * wv.w;
        }
        __syncthreads();
    }
    float4 bb = *reinterpret_cast<const float4*>(&b[cg]);
#pragma unroll
    for (int i = 0; i < 4; i++) {
        int r = r0 + rg4 + i;
        float4 o = make_float4(acc[i][0] + bb.x, acc[i][1] + bb.y,
                               acc[i][2] + bb.z, acc[i][3] + bb.w);
        *reinterpret_cast<float4*>(&C[(size_t)r * ldc + cg]) = o;
    }
}

// ---------------- triple GEMM (shared X, K = 256) --------------------------
__global__ __launch_bounds__(256)
void gemm3_bias_kernel(const float* __restrict__ X,
                       const float* __restrict__ W0, const float* __restrict__ b0, float* __restrict__ C0, int ldc0,
                       const float* __restrict__ W1, const float* __restrict__ b1, float* __restrict__ C1, int ldc1,
                       const float* __restrict__ W2, const float* __restrict__ b2, float* __restrict__ C2, int ldc2)
{
    __shared__ float Xs[GBK * 36];
    __shared__ float Ws[3 * GBK * 128];
    const int t   = threadIdx.x;
    const int r0  = blockIdx.x * 32;
    const int rg4 = (t >> 5) * 4;
    const int cg  = (t & 31) * 4;

    float acc[3][4][4];
#pragma unroll
    for (int w = 0; w < 3; w++)
#pragma unroll
        for (int i = 0; i < 4; i++)
#pragma unroll
            for (int j = 0; j < 4; j++) acc[w][i][j] = 0.f;

    const float* Wp[3] = {W0, W1, W2};

    for (int k0 = 0; k0 < IN_C; k0 += GBK) {
#pragma unroll
        for (int i = 0; i < 2; i++) {
            int idx = t + i * 256;
            int row = idx >> 4;
            int kk  = idx & 15;
            Xs[kk * 36 + row] = X[(size_t)(r0 + row) * IN_C + k0 + kk];
        }
#pragma unroll
        for (int w = 0; w < 3; w++) {
#pragma unroll
            for (int i = 0; i < 2; i++) {
                int row = (t >> 5) + i * 8;
                int col = (t & 31) * 4;
                float4 w4 = *reinterpret_cast<const float4*>(&Wp[w][(size_t)(k0 + row) * 128 + col]);
                *reinterpret_cast<float4*>(&Ws[w * GBK * 128 + row * 128 + col]) = w4;
            }
        }
        __syncthreads();
#pragma unroll
        for (int kk = 0; kk < GBK; kk++) {
            float4 xv = *reinterpret_cast<const float4*>(&Xs[kk * 36 + rg4]);
#pragma unroll
            for (int w = 0; w < 3; w++) {
                float4 wv = *reinterpret_cast<const float4*>(&Ws[w * GBK * 128 + kk * 128 + cg]);
                acc[w][0][0] += xv.x * wv.x; acc[w][0][1] += xv.x * wv.y; acc[w][0][2] += xv.x * wv.z; acc[w][0][3] += xv.x * wv.w;
                acc[w][1][0] += xv.y * wv.x; acc[w][1][1] += xv.y * wv.y; acc[w][1][2] += xv.y * wv.z; acc[w][1][3] += xv.y * wv.w;
                acc[w][2][0] += xv.z * wv.x; acc[w][2][1] += xv.z * wv.y; acc[w][2][2] += xv.z * wv.z; acc[w][2][3] += xv.z * wv.w;
                acc[w][3][0] += xv.w * wv.x; acc[w][3][1] += xv.w * wv.y; acc[w][3][2] += xv.w * wv.z; acc[w][3][3] += xv.w * wv.w;
            }
        }
        __syncthreads();
    }
    const float* bp[3] = {b0, b1, b2};
    float* Cp[3] = {C0, C1, C2};
    int ldcp[3] = {ldc0, ldc1, ldc2};
#pragma unroll
    for (int w = 0; w < 3; w++) {
        float4 bb = *reinterpret_cast<const float4*>(&bp[w][cg]);
#pragma unroll
        for (int i = 0; i < 4; i++) {
            int r = r0 + rg4 + i;
            float4 o = make_float4(acc[w][i][0] + bb.x, acc[w][i][1] + bb.y,
                                   acc[w][i][2] + bb.z, acc[w][i][3] + bb.w);
            *reinterpret_cast<float4*>(&Cp[w][(size_t)r * ldcp[w] + cg]) = o;
        }
    }
}

// ---------------- HMMA masked score GEMM -----------------------------------
// Block: 256 thr = 8 warps (4r x 2a) -> 128 r x 128 a tile, one head, K=64.
// Split-bf16: s = qh*kh + qh*kl + ql*kh via mma.sync.m16n8k16.
// smem rows padded to 88 bf16 (176 B) -> conflict-free b32 fragment loads.
#define SROW 88
#define SBUF (128 * SROW * 2)          // 22528 bytes per buffer
#define SC_SMEM (4 * SBUF)             // 90112 bytes

__global__ __launch_bounds__(256)
void scores_mma_kernel(const float* __restrict__ mask)
{
    extern __shared__ __nv_bfloat16 sm[];
    __nv_bfloat16* qh_s = sm;                       // [128][88]
    __nv_bfloat16* ql_s = sm + 128 * SROW;
    __nv_bfloat16* kh_s = sm + 2 * 128 * SROW;
    __nv_bfloat16* kl_s = sm + 3 * 128 * SROW;

    const int t    = threadIdx.x;
    const int lane = t & 31;
    const int wid  = t >> 5;
    const int wr   = wid >> 1;          // 0..3  warp row
    const int wa   = wid & 1;           // 0..1  warp col
    const int a0   = blockIdx.x * 128;
    const int r0   = blockIdx.y * 128;
    const int h    = blockIdx.z;

    // stage q/k hi+lo tiles: 128 rows x 64 bf16 each (uint4 = 8 bf16 chunks)
    const uint4* qh4 = reinterpret_cast<const uint4*>(g_qhi);
    const uint4* ql4 = reinterpret_cast<const uint4*>(g_qlo);
    const uint4* kh4 = reinterpret_cast<const uint4*>(g_khi);
    const uint4* kl4 = reinterpret_cast<const uint4*>(g_klo);
#pragma unroll
    for (int i = 0; i < 4; i++) {
        int id  = t + i * 256;          // 0..1023
        int row = id >> 3, ch = id & 7;
        int qg = (r0 + row) * (HID / 8) + h * 8 + ch;
        int kg = (a0 + row) * (HID / 8) + h * 8 + ch;
        *reinterpret_cast<uint4*>(&qh_s[row * SROW + ch * 8]) = qh4[qg];
        *reinterpret_cast<uint4*>(&ql_s[row * SROW + ch * 8]) = ql4[qg];
        *reinterpret_cast<uint4*>(&kh_s[row * SROW + ch * 8]) = kh4[kg];
        *reinterpret_cast<uint4*>(&kl_s[row * SROW + ch * 8]) = kl4[kg];
    }
    __syncthreads();

    float acc[2][8][4];
#pragma unroll
    for (int mi = 0; mi < 2; mi++)
#pragma unroll
        for (int ni = 0; ni < 8; ni++)
#pragma unroll
            for (int j = 0; j < 4; j++) acc[mi][ni][j] = 0.f;

    const int gid = lane >> 2;          // 0..7
    const int tig = lane & 3;           // 0..3

#pragma unroll
    for (int ks = 0; ks < 4; ks++) {
        const int kofs = ks * 16;
        // A fragments (q), hi and lo, for 2 m-atoms
        uint32_t Ah[2][4], Al[2][4];
#pragma unroll
        for (int mi = 0; mi < 2; mi++) {
            int r = wr * 32 + mi * 16 + gid;
            int c = kofs + tig * 2;
            Ah[mi][0] = *reinterpret_cast<const uint32_t*>(&qh_s[r * SROW + c]);
            Ah[mi][1] = *reinterpret_cast<const uint32_t*>(&qh_s[(r + 8) * SROW + c]);
            Ah[mi][2] = *reinterpret_cast<const uint32_t*>(&qh_s[r * SROW + c + 8]);
            Ah[mi][3] = *reinterpret_cast<const uint32_t*>(&qh_s[(r + 8) * SROW + c + 8]);
            Al[mi][0] = *reinterpret_cast<const uint32_t*>(&ql_s[r * SROW + c]);
            Al[mi][1] = *reinterpret_cast<const uint32_t*>(&ql_s[(r + 8) * SROW + c]);
            Al[mi][2] = *reinterpret_cast<const uint32_t*>(&ql_s[r * SROW + c + 8]);
            Al[mi][3] = *reinterpret_cast<const uint32_t*>(&ql_s[(r + 8) * SROW + c + 8]);
        }
        // B fragments (k), hi and lo, for 8 n-atoms
        uint32_t Bh[8][2], Bl[8][2];
#pragma unroll
        for (int ni = 0; ni < 8; ni++) {
            int n = wa * 64 + ni * 8 + gid;
            int k = kofs + tig * 2;
            Bh[ni][0] = *reinterpret_cast<const uint32_t*>(&kh_s[n * SROW + k]);
            Bh[ni][1] = *reinterpret_cast<const uint32_t*>(&kh_s[n * SROW + k + 8]);
            Bl[ni][0] = *reinterpret_cast<const uint32_t*>(&kl_s[n * SROW + k]);
            Bl[ni][1] = *reinterpret_cast<const uint32_t*>(&kl_s[n * SROW + k + 8]);
        }
#pragma unroll
        for (int mi = 0; mi < 2; mi++)
#pragma unroll
            for (int ni = 0; ni < 8; ni++) {
                mma_bf16(acc[mi][ni], Ah[mi], Bh[ni]);
                mma_bf16(acc[mi][ni], Ah[mi], Bl[ni]);
                mma_bf16(acc[mi][ni], Al[mi], Bh[ni]);
            }
    }

    // epilogue: multiply by mask, store to g_S
    const size_t Sbase = (size_t)h * N_RNA * N_ATAC;
#pragma unroll
    for (int mi = 0; mi < 2; mi++) {
        int rbase = r0 + wr * 32 + mi * 16 + gid;
#pragma unroll
        for (int ni = 0; ni < 8; ni++) {
            int c = a0 + wa * 64 + ni * 8 + tig * 2;
            {
                size_t off = (size_t)rbase * N_ATAC + c;
                float2 mm = *reinterpret_cast<const float2*>(mask + off);
                float2 o = make_float2(acc[mi][ni][0] * mm.x, acc[mi][ni][1] * mm.y);
                *reinterpret_cast<float2*>(g_S + Sbase + off) = o;
            }
            {
                size_t off = (size_t)(rbase + 8) * N_ATAC + c;
                float2 mm = *reinterpret_cast<const float2*>(mask + off);
                float2 o = make_float2(acc[mi][ni][2] * mm.x, acc[mi][ni][3] * mm.y);
                *reinterpret_cast<float2*>(g_S + Sbase + off) = o;
            }
        }
    }
}

// ---------------- single-pass top-k + softmax + gate + aggregation ---------
#define NCAND (256 * TOPK)
__global__ __launch_bounds__(256)
void topk_kernel()
{
    __shared__ float cv[NCAND];
    __shared__ int   ci[NCAND];
    __shared__ float redv[8];
    __shared__ int   redi[8], redp[8];
    __shared__ float topv[TOPK];
    __shared__ int   topi[TOPK];
    __shared__ float wsel[TOPK];

    const int r = blockIdx.x;
    const int h = blockIdx.y;
    const int t = threadIdx.x;
    const int lane = t & 31, w = t >> 5;

    const float4* row4 = reinterpret_cast<const float4*>(g_S + ((size_t)h * N_RNA + r) * N_ATAC);

    float lv[TOPK]; int li[TOPK];
#pragma unroll
    for (int j = 0; j < TOPK; j++) { lv[j] = -INFINITY; li[j] = 0x7FFFFFFF; }

#define TINS(val, ix) do { float _v = (val); \
    if (_v > lv[TOPK - 1]) { lv[TOPK - 1] = _v; li[TOPK - 1] = (ix); \
        _Pragma("unroll") \
        for (int _j = TOPK - 1; _j > 0; --_j) { \
            if (lv[_j] > lv[_j - 1]) { \
                float _tv = lv[_j]; lv[_j] = lv[_j - 1]; lv[_j - 1] = _tv; \
                int _ti = li[_j]; li[_j] = li[_j - 1]; li[_j - 1] = _ti; } } } } while (0)

#pragma unroll
    for (int it = 0; it < 8; it++) {
        int c4 = t + it * 256;
        float4 v = row4[c4];
        int b = c4 * 4;
        TINS(v.x, b); TINS(v.y, b + 1); TINS(v.z, b + 2); TINS(v.w, b + 3);
    }
#pragma unroll
    for (int j = 0; j < TOPK; j++) { cv[t * TOPK + j] = lv[j]; ci[t * TOPK + j] = li[j]; }
    __syncthreads();

    // 10 exact argmax passes over 2560 candidates (ties -> lowest a-index)
    for (int sel = 0; sel < TOPK; sel++) {
        float bv = -INFINITY; int bi = 0x7FFFFFFF; int bp = 0;
        for (int c = t; c < NCAND; c += 256) {
            float v = cv[c];
            int   i = ci[c];
            if (v > bv || (v == bv && i < bi)) { bv = v; bi = i; bp = c; }
        }
#pragma unroll
        for (int off = 16; off > 0; off >>= 1) {
            float ov = __shfl_down_sync(0xffffffffu, bv, off);
            int   oi = __shfl_down_sync(0xffffffffu, bi, off);
            int   op = __shfl_down_sync(0xffffffffu, bp, off);
            if (ov > bv || (ov == bv && oi < bi)) { bv = ov; bi = oi; bp = op; }
        }
        if (lane == 0) { redv[w] = bv; redi[w] = bi; redp[w] = bp; }
        __syncthreads();
        if (t == 0) {
            bv = redv[0]; bi = redi[0]; bp = redp[0];
#pragma unroll
            for (int ww = 1; ww < 8; ww++)
                if (redv[ww] > bv || (redv[ww] == bv && redi[ww] < bi)) {
                    bv = redv[ww]; bi = redi[ww]; bp = redp[ww];
                }
            topv[sel] = bv; topi[sel] = bi;
            cv[bp] = -INFINITY;
        }
        __syncthreads();
    }

    if (t == 0) {
        float p[TOPK], e[TOPK];
        float mx = -1e30f;
#pragma unroll
        for (int j = 0; j < TOPK; j++) {
            p[j] = 1.f / (1.f + expf(-topv[j]));
            if (p[j] > mx) mx = p[j];
        }
        float s = 0.f;
#pragma unroll
        for (int j = 0; j < TOPK; j++) { e[j] = expf(p[j] - mx); s += e[j]; }
#pragma unroll
        for (int j = 0; j < TOPK; j++) {
            float wgt = e[j] / s;
            if (!(p[j] > THR)) wgt = 0.f;
            wsel[j] = wgt;
        }
    }
    __syncthreads();

    if (t < DH) {
        float accd = 0.f;
        float vr = g_vr[(size_t)r * HID + h * DH + t];
#pragma unroll
        for (int j = 0; j < TOPK; j++) {
            float wgt = wsel[j];
            int   a = topi[j];
            if (wgt != 0.f) {
                accd += wgt * g_va[(size_t)a * HID + h * DH + t];
                atomicAdd(&g_aagg[(size_t)a * HID + h * DH + t], wgt * vr);
            }
        }
        g_ragg[(size_t)r * HID + h * DH + t] = accd;
    }
}

// ---------------------------------------------------------------------------
extern "C" void kernel_launch(void* const* d_in, const int* in_sizes, int n_in,
                              void* d_out, int out_size)
{
    const float* x_rna  = (const float*)d_in[0];
    const float* x_atac = (const float*)d_in[1];
    const float* cmask  = (const float*)d_in[2];
    const float* Wq  = (const float*)d_in[3];  const float* bq  = (const float*)d_in[4];
    const float* Wk  = (const float*)d_in[5];  const float* bk  = (const float*)d_in[6];
    const float* Wvr = (const float*)d_in[7];  const float* bvr = (const float*)d_in[8];
    const float* Wva = (const float*)d_in[9];  const float* bva = (const float*)d_in[10];
    const float* Wor = (const float*)d_in[11]; const float* bor = (const float*)d_in[12];
    const float* Woa = (const float*)d_in[13]; const float* boa = (const float*)d_in[14];
    const float* Wsr = (const float*)d_in[15]; const float* bsr = (const float*)d_in[16];
    const float* Wsa = (const float*)d_in[17]; const float* bsa = (const float*)d_in[18];
    const float* Wdr = (const float*)d_in[19]; const float* bdr = (const float*)d_in[20];
    const float* Wda = (const float*)d_in[21]; const float* bda = (const float*)d_in[22];
    float* out = (float*)d_out;

    float *q_p, *k_p, *vr_p, *va_p, *ragg_p, *aagg_p, *catr_p, *cata_p;
    __nv_bfloat16 *qhi_p, *qlo_p, *khi_p, *klo_p;
    cudaGetSymbolAddress((void**)&q_p,    g_q);
    cudaGetSymbolAddress((void**)&k_p,    g_k);
    cudaGetSymbolAddress((void**)&vr_p,   g_vr);
    cudaGetSymbolAddress((void**)&va_p,   g_va);
    cudaGetSymbolAddress((void**)&ragg_p, g_ragg);
    cudaGetSymbolAddress((void**)&aagg_p, g_aagg);
    cudaGetSymbolAddress((void**)&catr_p, g_catr);
    cudaGetSymbolAddress((void**)&cata_p, g_cata);
    cudaGetSymbolAddress((void**)&qhi_p,  g_qhi);
    cudaGetSymbolAddress((void**)&qlo_p,  g_qlo);
    cudaGetSymbolAddress((void**)&khi_p,  g_khi);
    cudaGetSymbolAddress((void**)&klo_p,  g_klo);

    zero_aagg_kernel<<<1024, 256>>>();

    // fused projections (3 outputs per input matrix)
    gemm3_bias_kernel<<<N_RNA / 32, 256>>>(x_rna,
        Wq,  bq,  q_p,  HID,
        Wvr, bvr, vr_p, HID,
        Wsr, bsr, catr_p + HID, 2 * HID);
    gemm3_bias_kernel<<<N_ATAC / 32, 256>>>(x_atac,
        Wk,  bk,  k_p,  HID,
        Wva, bva, va_p, HID,
        Wsa, bsa, cata_p + HID, 2 * HID);

    // split q/k to hi/lo bf16
    convert_kernel<<<(N_RNA  * HID) / 1024, 256>>>(q_p, qhi_p, qlo_p);
    convert_kernel<<<(N_ATAC * HID) / 1024, 256>>>(k_p, khi_p, klo_p);

    // tensor-core masked scores (HMMA mma.sync)
    cudaFuncSetAttribute(scores_mma_kernel, cudaFuncAttributeMaxDynamicSharedMemorySize, SC_SMEM);
    scores_mma_kernel<<<dim3(N_ATAC / 128, N_RNA / 128, NHEAD), 256, SC_SMEM>>>(cmask);

    // top-k + softmax + gate + aggregation
    topk_kernel<<<dim3(N_RNA, NHEAD), 256>>>();

    // output projections + concat + dim reduction
    gemm_bias_kernel<<<N_RNA  / 32, 256>>>(ragg_p, HID, Wor, bor, catr_p, 2 * HID);
    gemm_bias_kernel<<<N_ATAC / 32, 256>>>(aagg_p, HID, Woa, boa, cata_p, 2 * HID);
    gemm_bias_kernel<<<N_RNA  / 32, 256>>>(catr_p, 2 * HID, Wdr, bdr, out, HID);
    gemm_bias_kernel<<<N_ATAC / 32, 256>>>(cata_p, 2 * HID, Wda, bda, out + (size_t)N_RNA * HID, HID);
}